// round 13
// baseline (speedup 1.0000x reference)
#include <cuda_runtime.h>
#include <cuda_bf16.h>
#include <cstdint>

#define NTOK 4096
#define DHID 2048
#define IEXP 8192
#define NE   8
#define G1   64

// ---------------- scratch ----------------
__device__ float g_T[NTOK * G1];
__device__ float g_coef[NTOK * 4];
__device__ __nv_bfloat16 g_Xh[(size_t)NTOK * DHID];
__device__ __nv_bfloat16 g_Xl[(size_t)NTOK * DHID];
__device__ __nv_bfloat16 g_Wgh[(size_t)IEXP * DHID];   // w_gate^T planes [I][D]
__device__ __nv_bfloat16 g_Wgl[(size_t)IEXP * DHID];
__device__ __nv_bfloat16 g_Wuh[(size_t)IEXP * DHID];
__device__ __nv_bfloat16 g_Wul[(size_t)IEXP * DHID];
__device__ __nv_bfloat16 g_Wdh[(size_t)DHID * IEXP];   // w_down^T planes [D][I]
__device__ __nv_bfloat16 g_Wdl[(size_t)DHID * IEXP];
__device__ __nv_bfloat16 g_Hh[(size_t)NTOK * IEXP];
__device__ __nv_bfloat16 g_Hl[(size_t)NTOK * IEXP];

// ---------------- helpers ----------------
__device__ __forceinline__ float siluf(float z) { return z / (1.0f + __expf(-z)); }
__device__ __forceinline__ uint32_t smem_u32(const void* p) {
    uint32_t a;
    asm("{ .reg .u64 t; cvta.to.shared.u64 t, %1; cvt.u32.u64 %0, t; }" : "=r"(a) : "l"(p));
    return a;
}
__device__ __forceinline__ void cpa16(uint32_t d, const void* s) {
    asm volatile("cp.async.cg.shared.global [%0], [%1], 16;" :: "r"(d), "l"(s));
}
#define CPA_COMMIT() asm volatile("cp.async.commit_group;" ::: "memory")
#define CPA_WAIT(n)  asm volatile("cp.async.wait_group %0;" :: "n"(n) : "memory")

#define MMA_BF16(c, a, b)                                                        \
    asm volatile(                                                                \
        "mma.sync.aligned.m16n8k16.row.col.f32.bf16.bf16.f32 "                   \
        "{%0,%1,%2,%3}, {%4,%5,%6,%7}, {%8,%9}, {%0,%1,%2,%3};"                  \
        : "+f"((c)[0]), "+f"((c)[1]), "+f"((c)[2]), "+f"((c)[3])                 \
        : "r"((a)[0]), "r"((a)[1]), "r"((a)[2]), "r"((a)[3]),                    \
          "r"((b)[0]), "r"((b)[1]))

// per stage (uint32 words): A 128x36 = 4608 (hi words 0..15, lo 16..31, pad),
// B 128x36 = 4608 -> 9216 words/stage
#define OFF_A(s) ((s) * 9216)
#define OFF_B(s) ((s) * 9216 + 4608)
#define SMEM_BYTES (2 * 9216 * 4)   // 73728 B, 2 stages -> 2 CTAs/SM (16 warps)

// ======================================================================
// Prep: elementwise fp32 -> (hi, lo) bf16 split
// ======================================================================
__global__ __launch_bounds__(256) void split_bf16_k(
    const float* __restrict__ src, __nv_bfloat16* __restrict__ hi,
    __nv_bfloat16* __restrict__ lo, int n4)
{
    int i = blockIdx.x * blockDim.x + threadIdx.x;
    int stride = gridDim.x * blockDim.x;
    for (; i < n4; i += stride) {
        float4 v = ((const float4*)src)[i];
        __nv_bfloat16 h0 = __float2bfloat16(v.x);
        __nv_bfloat16 h1 = __float2bfloat16(v.y);
        __nv_bfloat16 h2 = __float2bfloat16(v.z);
        __nv_bfloat16 h3 = __float2bfloat16(v.w);
        __nv_bfloat16 l0 = __float2bfloat16(v.x - __bfloat162float(h0));
        __nv_bfloat16 l1 = __float2bfloat16(v.y - __bfloat162float(h1));
        __nv_bfloat16 l2 = __float2bfloat16(v.z - __bfloat162float(h2));
        __nv_bfloat16 l3 = __float2bfloat16(v.w - __bfloat162float(h3));
        uint2 ph, pl;
        ph.x = (uint32_t)__bfloat16_as_ushort(h0) | ((uint32_t)__bfloat16_as_ushort(h1) << 16);
        ph.y = (uint32_t)__bfloat16_as_ushort(h2) | ((uint32_t)__bfloat16_as_ushort(h3) << 16);
        pl.x = (uint32_t)__bfloat16_as_ushort(l0) | ((uint32_t)__bfloat16_as_ushort(l1) << 16);
        pl.y = (uint32_t)__bfloat16_as_ushort(l2) | ((uint32_t)__bfloat16_as_ushort(l3) << 16);
        ((uint2*)hi)[i] = ph;
        ((uint2*)lo)[i] = pl;
    }
}

// Prep: transpose + split. src [R][C] fp32 -> dst_hi/lo [C][R] bf16
__global__ __launch_bounds__(256) void transpose_split_k(
    const float* __restrict__ src, __nv_bfloat16* __restrict__ dhi,
    __nv_bfloat16* __restrict__ dlo, int R, int C)
{
    __shared__ float t[32][33];
    int c0 = blockIdx.x * 32, r0 = blockIdx.y * 32;
    int tx = threadIdx.x, ty = threadIdx.y;
    #pragma unroll
    for (int j = 0; j < 32; j += 8)
        t[ty + j][tx] = src[(size_t)(r0 + ty + j) * C + c0 + tx];
    __syncthreads();
    #pragma unroll
    for (int j = 0; j < 32; j += 8) {
        float v = t[tx][ty + j];
        __nv_bfloat16 h = __float2bfloat16(v);
        __nv_bfloat16 l = __float2bfloat16(v - __bfloat162float(h));
        dhi[(size_t)(c0 + ty + j) * R + r0 + tx] = h;
        dlo[(size_t)(c0 + ty + j) * R + r0 + tx] = l;
    }
}

// ======================================================================
// Router stage A: T = tanh(X @ gate_w1)
// ======================================================================
__global__ __launch_bounds__(256) void router_gemm_tanh(
    const float* __restrict__ X, const float* __restrict__ W1)
{
    __shared__ float Xs[32][65];
    __shared__ float Ws[32][64];
    const int tid = threadIdx.x;
    const int tx = tid & 15, ty = tid >> 4;
    const int m0 = blockIdx.x * 64;

    float acc[4][4] = {};
    for (int k0 = 0; k0 < DHID; k0 += 32) {
        __syncthreads();
        #pragma unroll
        for (int i = 0; i < 8; i++) {
            int e = tid + i * 256;
            Xs[e & 31][e >> 5] = X[(size_t)(m0 + (e >> 5)) * DHID + k0 + (e & 31)];
        }
        #pragma unroll
        for (int i = 0; i < 8; i++) {
            int e = tid + i * 256;
            Ws[e >> 6][e & 63] = W1[(size_t)(k0 + (e >> 6)) * G1 + (e & 63)];
        }
        __syncthreads();
        #pragma unroll
        for (int k = 0; k < 32; k++) {
            float av[4], bv[4];
            #pragma unroll
            for (int i = 0; i < 4; i++) av[i] = Xs[k][ty * 4 + i];
            #pragma unroll
            for (int j = 0; j < 4; j++) bv[j] = Ws[k][tx * 4 + j];
            #pragma unroll
            for (int i = 0; i < 4; i++)
                #pragma unroll
                for (int j = 0; j < 4; j++)
                    acc[i][j] = fmaf(av[i], bv[j], acc[i][j]);
        }
    }
    #pragma unroll
    for (int i = 0; i < 4; i++)
        #pragma unroll
        for (int j = 0; j < 4; j++)
            g_T[(size_t)(m0 + ty * 4 + i) * G1 + tx * 4 + j] = tanhf(acc[i][j]);
}

// ======================================================================
// Router stage B
// ======================================================================
__global__ __launch_bounds__(128) void router_combine(
    const float* __restrict__ X, const float* __restrict__ W2,
    const float* __restrict__ ceWg, float* __restrict__ logits_out)
{
    const int n = blockIdx.x;
    const int tid = threadIdx.x;
    __shared__ float red[4][128];
    __shared__ float lg[8];

    float pg0 = 0.f, pg1 = 0.f, pg2 = 0.f, pg3 = 0.f;
    for (int k = tid; k < DHID; k += 128) {
        float xv = X[(size_t)n * DHID + k];
        pg0 = fmaf(xv, ceWg[k * 2 + 0], pg0);
        pg1 = fmaf(xv, ceWg[k * 2 + 1], pg1);
        pg2 = fmaf(xv, ceWg[DHID * 2 + k * 2 + 0], pg2);
        pg3 = fmaf(xv, ceWg[DHID * 2 + k * 2 + 1], pg3);
    }
    red[0][tid] = pg0; red[1][tid] = pg1; red[2][tid] = pg2; red[3][tid] = pg3;
    __syncthreads();
    for (int s = 64; s > 0; s >>= 1) {
        if (tid < s) {
            #pragma unroll
            for (int j = 0; j < 4; j++) red[j][tid] += red[j][tid + s];
        }
        __syncthreads();
    }
    if (tid < NE) {
        float s = 0.f;
        #pragma unroll 8
        for (int i = 0; i < G1; i++)
            s = fmaf(g_T[(size_t)n * G1 + i], W2[i * NE + tid], s);
        lg[tid] = s;
        logits_out[(size_t)n * NE + tid] = s;
    }
    __syncthreads();
    if (tid == 0) {
        float p[NE];
        float mx = lg[0];
        #pragma unroll
        for (int e = 1; e < NE; e++) mx = fmaxf(mx, lg[e]);
        float sum = 0.f;
        #pragma unroll
        for (int e = 0; e < NE; e++) { p[e] = __expf(lg[e] - mx); sum += p[e]; }
        float inv = 1.f / sum;
        #pragma unroll
        for (int e = 0; e < NE; e++) p[e] *= inv;
        int i0 = 0;
        #pragma unroll
        for (int e = 1; e < NE; e++) if (p[e] > p[i0]) i0 = e;
        int i1 = (i0 == 0) ? 1 : 0;
        #pragma unroll
        for (int e = 0; e < NE; e++) if (e != i0 && p[e] > p[i1]) i1 = e;
        float w0 = (i0 == NE - 1) ? 0.f : p[i0];
        float w1 = (i1 == NE - 1) ? 0.f : p[i1];
        float winv = 1.f / (w0 + w1);
        w0 *= winv; w1 *= winv;
        float pe[NE];
        #pragma unroll
        for (int e = 0; e < NE; e++) pe[e] = 0.f;
        pe[i0] += w0; pe[i1] += w1;
        float cw0x = 1.f / (1.f + __expf(red[1][0] - red[0][0]));
        float cw1x = 1.f / (1.f + __expf(red[3][0] - red[2][0]));
        g_coef[n * 4 + 0] = pe[0] + pe[2] * cw0x + pe[3] * cw1x;
        g_coef[n * 4 + 1] = pe[2] * (1.f - cw0x);
        g_coef[n * 4 + 2] = pe[3] * (1.f - cw1x);
        g_coef[n * 4 + 3] = pe[4] + pe[5] + pe[6] + pe[7];
    }
}

// ======================================================================
// GEMM 1: H = silu(X@Wg) * (X@Wu), bf16x3 split precision
// CTA: 256 threads (8 warps, 2x4), CTA tile M=128 x mmaN=128 (G|U 64 each).
// Warp tile m64 x n32. 2-stage cp.async, 2 CTAs/SM.
// ======================================================================
__global__ __launch_bounds__(256, 2) void gemm_gateup()
{
    extern __shared__ unsigned sm[];
    const uint32_t sa = smem_u32(sm);
    const int tid = threadIdx.x;
    const int lane = tid & 31, wid = tid >> 5;
    const int wm = wid & 1, wn = wid >> 1;          // 2x4
    const int g = lane >> 2, tg = lane & 3;
    const int m0 = blockIdx.x * 128;
    const int n0 = blockIdx.y * 64;
    const int KT = DHID / 32;

    float acc[4][4][4] = {};   // [mi][ni][4]

    auto issue = [&](int kt) {
        int s = kt & 1, k0 = kt * 32;
        #pragma unroll
        for (int i = 0; i < 4; i++) {                 // A: 128 rows x 8 chunks
            int e = tid + i * 256;
            int r = e >> 3, c = e & 7;
            uint32_t dst = sa + (OFF_A(s) + r * 36 + ((c < 4) ? c * 4 : 16 + (c - 4) * 4)) * 4;
            const __nv_bfloat16* base = (c < 4) ? g_Xh : g_Xl;
            cpa16(dst, base + (size_t)(m0 + r) * DHID + k0 + (c & 3) * 8);
        }
        #pragma unroll
        for (int i = 0; i < 4; i++) {                 // B: 128 n-rows x 8 chunks
            int e = tid + i * 256;
            int n = e >> 3, c = e & 7;
            const __nv_bfloat16* base;
            int ncol;
            if (n < 64) { base = (c < 4) ? g_Wgh : g_Wgl; ncol = n0 + n; }
            else        { base = (c < 4) ? g_Wuh : g_Wul; ncol = n0 + n - 64; }
            uint32_t dst = sa + (OFF_B(s) + n * 36 + ((c < 4) ? c * 4 : 16 + (c - 4) * 4)) * 4;
            cpa16(dst, base + (size_t)ncol * DHID + k0 + (c & 3) * 8);
        }
        CPA_COMMIT();
    };

    issue(0);
    const int arow = wm * 64;
    const int bcol = wn * 32;

    for (int kt = 0; kt < KT; kt++) {
        CPA_WAIT(0);
        __syncthreads();
        if (kt + 1 < KT) issue(kt + 1);
        const unsigned* As = sm + OFF_A(kt & 1);
        const unsigned* Bs = sm + OFF_B(kt & 1);
        #pragma unroll
        for (int s2 = 0; s2 < 2; s2++) {              // two k16 steps per k32 tile
            int w = s2 * 8 + tg;
            unsigned ah[4][4], bh[4][2];
            #pragma unroll
            for (int mi = 0; mi < 4; mi++) {
                int r = arow + mi * 16 + g;
                ah[mi][0] = As[r * 36 + w];
                ah[mi][1] = As[(r + 8) * 36 + w];
                ah[mi][2] = As[r * 36 + w + 4];
                ah[mi][3] = As[(r + 8) * 36 + w + 4];
            }
            #pragma unroll
            for (int ni = 0; ni < 4; ni++) {
                int nn = bcol + ni * 8 + g;
                bh[ni][0] = Bs[nn * 36 + w];
                bh[ni][1] = Bs[nn * 36 + w + 4];
            }
            #pragma unroll
            for (int mi = 0; mi < 4; mi++)
                #pragma unroll
                for (int ni = 0; ni < 4; ni++)
                    MMA_BF16(acc[mi][ni], ah[mi], bh[ni]);
            unsigned bl[4][2];
            #pragma unroll
            for (int ni = 0; ni < 4; ni++) {
                int nn = bcol + ni * 8 + g;
                bl[ni][0] = Bs[nn * 36 + 16 + w];
                bl[ni][1] = Bs[nn * 36 + 16 + w + 4];
            }
            #pragma unroll
            for (int mi = 0; mi < 4; mi++)
                #pragma unroll
                for (int ni = 0; ni < 4; ni++)
                    MMA_BF16(acc[mi][ni], ah[mi], bl[ni]);
            unsigned al[4][4];
            #pragma unroll
            for (int mi = 0; mi < 4; mi++) {
                int r = arow + mi * 16 + g;
                al[mi][0] = As[r * 36 + 16 + w];
                al[mi][1] = As[(r + 8) * 36 + 16 + w];
                al[mi][2] = As[r * 36 + 16 + w + 4];
                al[mi][3] = As[(r + 8) * 36 + 16 + w + 4];
            }
            #pragma unroll
            for (int mi = 0; mi < 4; mi++)
                #pragma unroll
                for (int ni = 0; ni < 4; ni++)
                    MMA_BF16(acc[mi][ni], al[mi], bh[ni]);
        }
    }
    __syncthreads();

    // epilogue: acc -> smem [128][132] fp32, pair G/U, split H to bf16 planes
    float* Hs = (float*)sm;
    #pragma unroll
    for (int mi = 0; mi < 4; mi++) {
        int r1 = arow + mi * 16 + g, r2 = r1 + 8;
        #pragma unroll
        for (int ni = 0; ni < 4; ni++) {
            int cc = bcol + ni * 8 + 2 * tg;
            float* c = acc[mi][ni];
            *(float2*)(Hs + r1 * 132 + cc) = make_float2(c[0], c[1]);
            *(float2*)(Hs + r2 * 132 + cc) = make_float2(c[2], c[3]);
        }
    }
    __syncthreads();
    #pragma unroll
    for (int i = 0; i < 32; i++) {
        int e = tid + i * 256;
        int r = e >> 6, cc = e & 63;
        float gv = Hs[r * 132 + cc];
        float uv = Hs[r * 132 + 64 + cc];
        float h = siluf(gv) * uv;
        __nv_bfloat16 hh = __float2bfloat16(h);
        __nv_bfloat16 hl = __float2bfloat16(h - __bfloat162float(hh));
        size_t o = (size_t)(m0 + r) * IEXP + n0 + cc;
        g_Hh[o] = hh;
        g_Hl[o] = hl;
    }
}

// ======================================================================
// GEMM 2: out = cs*(H@Wd) + cx*x + cc0*c0 + cc1*c1, bf16x3
// CTA: 256 threads (8 warps, 2x4), tile M=128 x N=128. Warp tile m64xn32.
// ======================================================================
__global__ __launch_bounds__(256, 2) void gemm_down(
    const float* __restrict__ X,
    const float* __restrict__ ceC,
    float* __restrict__ out)
{
    extern __shared__ unsigned sm[];
    const uint32_t sa = smem_u32(sm);
    const int tid = threadIdx.x;
    const int lane = tid & 31, wid = tid >> 5;
    const int wm = wid & 1, wn = wid >> 1;
    const int g = lane >> 2, tg = lane & 3;
    const int m0 = blockIdx.x * 128;
    const int n0 = blockIdx.y * 128;
    const int KT = IEXP / 32;

    float acc[4][4][4] = {};

    auto issue = [&](int kt) {
        int s = kt & 1, k0 = kt * 32;
        #pragma unroll
        for (int i = 0; i < 4; i++) {                 // A from H planes
            int e = tid + i * 256;
            int r = e >> 3, c = e & 7;
            uint32_t dst = sa + (OFF_A(s) + r * 36 + ((c < 4) ? c * 4 : 16 + (c - 4) * 4)) * 4;
            const __nv_bfloat16* base = (c < 4) ? g_Hh : g_Hl;
            cpa16(dst, base + (size_t)(m0 + r) * IEXP + k0 + (c & 3) * 8);
        }
        #pragma unroll
        for (int i = 0; i < 4; i++) {                 // B from WdT planes
            int e = tid + i * 256;
            int n = e >> 3, c = e & 7;
            const __nv_bfloat16* base = (c < 4) ? g_Wdh : g_Wdl;
            uint32_t dst = sa + (OFF_B(s) + n * 36 + ((c < 4) ? c * 4 : 16 + (c - 4) * 4)) * 4;
            cpa16(dst, base + (size_t)(n0 + n) * IEXP + k0 + (c & 3) * 8);
        }
        CPA_COMMIT();
    };

    issue(0);
    const int arow = wm * 64;
    const int bcol = wn * 32;

    for (int kt = 0; kt < KT; kt++) {
        CPA_WAIT(0);
        __syncthreads();
        if (kt + 1 < KT) issue(kt + 1);
        const unsigned* As = sm + OFF_A(kt & 1);
        const unsigned* Bs = sm + OFF_B(kt & 1);
        #pragma unroll
        for (int s2 = 0; s2 < 2; s2++) {
            int w = s2 * 8 + tg;
            unsigned ah[4][4], bh[4][2];
            #pragma unroll
            for (int mi = 0; mi < 4; mi++) {
                int r = arow + mi * 16 + g;
                ah[mi][0] = As[r * 36 + w];
                ah[mi][1] = As[(r + 8) * 36 + w];
                ah[mi][2] = As[r * 36 + w + 4];
                ah[mi][3] = As[(r + 8) * 36 + w + 4];
            }
            #pragma unroll
            for (int ni = 0; ni < 4; ni++) {
                int nn = bcol + ni * 8 + g;
                bh[ni][0] = Bs[nn * 36 + w];
                bh[ni][1] = Bs[nn * 36 + w + 4];
            }
            #pragma unroll
            for (int mi = 0; mi < 4; mi++)
                #pragma unroll
                for (int ni = 0; ni < 4; ni++)
                    MMA_BF16(acc[mi][ni], ah[mi], bh[ni]);
            unsigned bl[4][2];
            #pragma unroll
            for (int ni = 0; ni < 4; ni++) {
                int nn = bcol + ni * 8 + g;
                bl[ni][0] = Bs[nn * 36 + 16 + w];
                bl[ni][1] = Bs[nn * 36 + 16 + w + 4];
            }
            #pragma unroll
            for (int mi = 0; mi < 4; mi++)
                #pragma unroll
                for (int ni = 0; ni < 4; ni++)
                    MMA_BF16(acc[mi][ni], ah[mi], bl[ni]);
            unsigned al[4][4];
            #pragma unroll
            for (int mi = 0; mi < 4; mi++) {
                int r = arow + mi * 16 + g;
                al[mi][0] = As[r * 36 + 16 + w];
                al[mi][1] = As[(r + 8) * 36 + 16 + w];
                al[mi][2] = As[r * 36 + 16 + w + 4];
                al[mi][3] = As[(r + 8) * 36 + 16 + w + 4];
            }
            #pragma unroll
            for (int mi = 0; mi < 4; mi++)
                #pragma unroll
                for (int ni = 0; ni < 4; ni++)
                    MMA_BF16(acc[mi][ni], al[mi], bh[ni]);
        }
    }

    // epilogue: fold routing coefficients, direct from regs
    const float* c0 = ceC;
    const float* c1 = ceC + DHID;
    #pragma unroll
    for (int mi = 0; mi < 4; mi++) {
        int r1 = m0 + arow + mi * 16 + g;
        int r2 = r1 + 8;
        float cx1 = g_coef[r1 * 4 + 0], cc01 = g_coef[r1 * 4 + 1],
              cc11 = g_coef[r1 * 4 + 2], cs1 = g_coef[r1 * 4 + 3];
        float cx2 = g_coef[r2 * 4 + 0], cc02 = g_coef[r2 * 4 + 1],
              cc12 = g_coef[r2 * 4 + 2], cs2 = g_coef[r2 * 4 + 3];
        #pragma unroll
        for (int ni = 0; ni < 4; ni++) {
            int nn = n0 + bcol + ni * 8 + 2 * tg;
            float* c = acc[mi][ni];
            float2 x1 = *(const float2*)(X + (size_t)r1 * DHID + nn);
            float2 x2 = *(const float2*)(X + (size_t)r2 * DHID + nn);
            float2 v0 = *(const float2*)(c0 + nn);
            float2 v1 = *(const float2*)(c1 + nn);
            float2 o1, o2;
            o1.x = cs1 * c[0] + cx1 * x1.x + cc01 * v0.x + cc11 * v1.x;
            o1.y = cs1 * c[1] + cx1 * x1.y + cc01 * v0.y + cc11 * v1.y;
            o2.x = cs2 * c[2] + cx2 * x2.x + cc02 * v0.x + cc12 * v1.x;
            o2.y = cs2 * c[3] + cx2 * x2.y + cc02 * v0.y + cc12 * v1.y;
            *(float2*)(out + (size_t)r1 * DHID + nn) = o1;
            *(float2*)(out + (size_t)r2 * DHID + nn) = o2;
        }
    }
}

// ======================================================================
extern "C" void kernel_launch(void* const* d_in, const int* in_sizes, int n_in,
                              void* d_out, int out_size)
{
    const float* X    = (const float*)d_in[0];
    const float* W1   = (const float*)d_in[1];
    const float* W2   = (const float*)d_in[2];
    const float* ceWg = (const float*)d_in[3];
    const float* ceC  = (const float*)d_in[4];
    const float* Wg   = (const float*)d_in[5];
    const float* Wu   = (const float*)d_in[6];
    const float* Wd   = (const float*)d_in[7];
    float* out = (float*)d_out;
    float* logits = out + (size_t)NTOK * DHID;

    cudaFuncSetAttribute(gemm_gateup, cudaFuncAttributeMaxDynamicSharedMemorySize, SMEM_BYTES);
    cudaFuncSetAttribute(gemm_down, cudaFuncAttributeMaxDynamicSharedMemorySize, SMEM_BYTES);

    __nv_bfloat16 *pXh, *pXl, *pWgh, *pWgl, *pWuh, *pWul, *pWdh, *pWdl;
    cudaGetSymbolAddress((void**)&pXh, g_Xh);
    cudaGetSymbolAddress((void**)&pXl, g_Xl);
    cudaGetSymbolAddress((void**)&pWgh, g_Wgh);
    cudaGetSymbolAddress((void**)&pWgl, g_Wgl);
    cudaGetSymbolAddress((void**)&pWuh, g_Wuh);
    cudaGetSymbolAddress((void**)&pWul, g_Wul);
    cudaGetSymbolAddress((void**)&pWdh, g_Wdh);
    cudaGetSymbolAddress((void**)&pWdl, g_Wdl);

    // prep: split X elementwise; transpose+split weights to n-major planes
    split_bf16_k<<<1024, 256>>>(X, pXh, pXl, NTOK * DHID / 4);
    transpose_split_k<<<dim3(IEXP / 32, DHID / 32), dim3(32, 8)>>>(Wg, pWgh, pWgl, DHID, IEXP);
    transpose_split_k<<<dim3(IEXP / 32, DHID / 32), dim3(32, 8)>>>(Wu, pWuh, pWul, DHID, IEXP);
    transpose_split_k<<<dim3(DHID / 32, IEXP / 32), dim3(32, 8)>>>(Wd, pWdh, pWdl, IEXP, DHID);

    // router
    router_gemm_tanh<<<NTOK / 64, 256>>>(X, W1);
    gemm_gateup<<<dim3(NTOK / 128, IEXP / 64), 256, SMEM_BYTES>>>();
    router_combine<<<NTOK, 128>>>(X, W2, ceWg, logits);
    gemm_down<<<dim3(NTOK / 128, DHID / 128), 256, SMEM_BYTES>>>(X, ceC, out);
}